// round 12
// baseline (speedup 1.0000x reference)
#include <cuda_runtime.h>
#include <cuda_bf16.h>
#include <mma.h>
#include <cstdint>

using namespace nvcuda;

typedef unsigned long long ULL;

// bf16 hi/lo split weights: [variant(0=hi,1=lo)][tap(9)][c(32)][oc(32)]
__device__ unsigned short g_bw[18432];

// ---------------------------------------------------------------------------
// Kernel 1: sigma = max(1, s1/2) via repeated squaring + Rayleigh quotient,
// then emit bf16 hi/lo split weights into g_bw (layout [v][tap][c][oc]).
// ---------------------------------------------------------------------------
#define WT_STRIDE 33

__global__ void sigma_kernel(const float* __restrict__ w_bar) {
    __shared__ float Wt[288 * WT_STRIDE];
    __shared__ float G0[1024];
    __shared__ float s_inv;

    int tid = threadIdx.x;

    for (int m = tid; m < 9216; m += 256) {
        int i = m / 288;
        int k = m - i * 288;
        Wt[k * WT_STRIDE + i] = w_bar[m];
    }
    __syncthreads();

    for (int e = tid; e < 1024; e += 256) {
        int i = e >> 5, j = e & 31;
        float s = 0.f;
        #pragma unroll 4
        for (int k = 0; k < 288; ++k)
            s += Wt[k * WT_STRIDE + i] * Wt[k * WT_STRIDE + j];
        G0[e] = s;
    }
    __syncthreads();

    float* bufA = Wt;
    float* bufB = Wt + 1024;

    const float* cur = G0;
    float* nxt = bufA;
    for (int it = 0; it < 14; ++it) {
        float tr = 0.f;
        #pragma unroll
        for (int d = 0; d < 32; ++d) tr += cur[d * 33];
        float inv = 1.0f / fmaxf(tr, 1e-30f);
        float inv2 = inv * inv;

        for (int e = tid; e < 1024; e += 256) {
            int i = e >> 5, j = e & 31;
            const float* ri = cur + i * 32;
            float s = 0.f;
            #pragma unroll
            for (int k = 0; k < 32; ++k) s += ri[k] * cur[k * 32 + j];
            nxt[e] = s * inv2;
        }
        __syncthreads();
        cur = nxt;
        nxt = (nxt == bufA) ? bufB : bufA;
    }

    if (tid < 32) {
        float d = cur[tid * 33];
        int jbest = tid;
        #pragma unroll
        for (int off = 16; off > 0; off >>= 1) {
            float od = __shfl_xor_sync(0xffffffffu, d, off);
            int   oj = __shfl_xor_sync(0xffffffffu, jbest, off);
            if (od > d) { d = od; jbest = oj; }
        }
        jbest = __shfl_sync(0xffffffffu, jbest, 0);

        float v = cur[tid * 32 + jbest];
        float gv = 0.f;
        const float* gi = G0 + tid * 32;
        #pragma unroll
        for (int j = 0; j < 32; ++j)
            gv += gi[j] * __shfl_sync(0xffffffffu, v, j);

        float num = v * gv, den = v * v;
        #pragma unroll
        for (int off = 16; off > 0; off >>= 1) {
            num += __shfl_xor_sync(0xffffffffu, num, off);
            den += __shfl_xor_sync(0xffffffffu, den, off);
        }
        if (tid == 0) {
            float lambda1 = num / fmaxf(den, 1e-30f);  // = s1^2
            float s1 = sqrtf(fmaxf(lambda1, 0.f));
            float sigma = fmaxf(1.0f, 0.5f * s1);
            s_inv = 1.0f / sigma;
        }
    }
    __syncthreads();

    float invs = s_inv;
    for (int i = tid; i < 9216; i += 256) {
        int oc  = i / 288;
        int rem = i - oc * 288;      // c*9 + ky*3 + kx
        int c   = rem / 9;
        int k9  = rem - c * 9;
        float w = w_bar[i] * invs;
        __nv_bfloat16 h = __float2bfloat16(w);
        float hv = __bfloat162float(h);
        __nv_bfloat16 l = __float2bfloat16(w - hv);
        int idx = (k9 * 32 + c) * 32 + oc;   // [tap][c][oc]
        g_bw[idx]        = __bfloat16_as_ushort(h);
        g_bw[idx + 9216] = __bfloat16_as_ushort(l);
    }
}

// ---------------------------------------------------------------------------
// Kernel 2: WMMA bf16 conv (3-term hi/lo split: xh*wh + xl*wh + xh*wl).
//
// A (x) strips: ring of 4 slots, one per input row; each slot holds hi and lo
// bf16 planes [130 px][40 (c, ldm)] (80B rows -> conflict-free ldmatrix).
// B (w): 18 mats [c=32][oc->40 ldm] bf16 (hi taps 0..8, lo taps 9..17).
// Tile = one output row: M=128 px x N=32 oc, K=32 per tap, 9 taps, 3 terms.
// Warps 0-3 compute (32px x 32oc each, acc seeded with bias, direct gmem
// store_matrix_sync); warps 4-7 stage row t+2 of the ring.
// ---------------------------------------------------------------------------
#define SLOT_ELEMS 10400          // 2 planes x 130 x 40 bf16
#define PLANE      5200
#define B_ELEMS    23040          // 18 x 32 x 40
#define BIAS_F     640            // 2 tiles x 16 x 20 f32
#define SMEM_DYN   ((4 * SLOT_ELEMS + B_ELEMS) * 2 + BIAS_F * 4)  // 131840

typedef wmma::fragment<wmma::matrix_a, 16, 16, 16, __nv_bfloat16, wmma::row_major> FragA;
typedef wmma::fragment<wmma::matrix_b, 16, 16, 16, __nv_bfloat16, wmma::row_major> FragB;
typedef wmma::fragment<wmma::accumulator, 16, 16, 16, float> FragC;

extern __shared__ __nv_bfloat16 s_bf[];

// stage input row `row` into ring slot `sl` as hi/lo bf16 planes
__device__ __forceinline__ void stage_strip(__nv_bfloat16* sl, int row, int x0,
                                            const float* xn, int lt, int nthr) {
    __nv_bfloat16* hi = sl;
    __nv_bfloat16* lo = sl + PLANE;
    bool rv = ((unsigned)row < 256u);
    const float* rp = xn + (rv ? row : 0) * 256;
    #pragma unroll 1
    for (int e = lt; e < 4160; e += nthr) {
        int c  = e / 130;
        int px = e - c * 130;
        int gx = x0 - 1 + px;
        float v = (rv && (unsigned)gx < 256u) ? __ldg(rp + c * 65536 + gx) : 0.f;
        __nv_bfloat16 h = __float2bfloat16(v);
        float hf = __bfloat162float(h);
        __nv_bfloat16 l = __float2bfloat16(v - hf);
        hi[px * 40 + c] = h;
        lo[px * 40 + c] = l;
    }
}

__global__ __launch_bounds__(256, 1)
void conv_wmma(const float* __restrict__ x,
               const float* __restrict__ bias,
               float* __restrict__ out) {
    __nv_bfloat16* sA = s_bf;                       // 4 slots
    __nv_bfloat16* sB = s_bf + 4 * SLOT_ELEMS;      // 18 mats
    float* sbias = (float*)(s_bf + 4 * SLOT_ELEMS + B_ELEMS);

    int tid = threadIdx.x, wid = tid >> 5;

    int bx = blockIdx.x;              // 512 CTAs
    int n  = bx >> 4;
    int xt = (bx >> 3) & 1;
    int yq = bx & 7;
    int x0 = xt * 128;
    int y0 = yq * 32;
    const float* xn = x + (size_t)n * 2097152u;

    // stage B (all 18 mats), bias tiles, and prestage strips y0-1..y0+1
    for (int e = tid; e < 18432; e += 256) {
        int mat = e >> 10;
        int c   = (e >> 5) & 31;
        int oc  = e & 31;
        sB[mat * 1280 + c * 40 + oc] = __ushort_as_bfloat16(g_bw[e]);
    }
    for (int e = tid; e < BIAS_F; e += 256) {
        int nf = e / 320;
        int j  = e % 20;
        sbias[e] = (j < 16) ? bias[nf * 16 + j] : 0.f;
    }
    #pragma unroll
    for (int s = 0; s < 3; ++s)       // strips y0-1, y0, y0+1 -> slots 0,1,2
        stage_strip(sA + s * SLOT_ELEMS, y0 - 1 + s, x0, xn, tid, 256);
    __syncthreads();

    #pragma unroll 1
    for (int t = 0; t < 32; ++t) {
        if (wid < 4) {
            int px0 = wid * 32;
            FragC acc[2][2];
            #pragma unroll
            for (int m = 0; m < 2; ++m)
                #pragma unroll
                for (int nf = 0; nf < 2; ++nf)
                    wmma::load_matrix_sync(acc[m][nf], sbias + nf * 320, 20,
                                           wmma::mem_row_major);

            #pragma unroll 1
            for (int ky = 0; ky < 3; ++ky) {
                const __nv_bfloat16* slot = sA + ((t + ky) & 3) * SLOT_ELEMS;
                #pragma unroll 1
                for (int kx = 0; kx < 3; ++kx) {
                    const __nv_bfloat16* bh = sB + (ky * 3 + kx) * 1280;
                    const __nv_bfloat16* bl = bh + 9 * 1280;
                    #pragma unroll
                    for (int kt = 0; kt < 2; ++kt) {
                        FragA ah[2], al[2];
                        #pragma unroll
                        for (int m = 0; m < 2; ++m) {
                            const __nv_bfloat16* ap =
                                slot + (px0 + m * 16 + kx) * 40 + kt * 16;
                            wmma::load_matrix_sync(ah[m], ap, 40);
                            wmma::load_matrix_sync(al[m], ap + PLANE, 40);
                        }
                        FragB fbh[2], fbl[2];
                        #pragma unroll
                        for (int nf = 0; nf < 2; ++nf) {
                            const __nv_bfloat16* bp = bh + kt * 16 * 40 + nf * 16;
                            wmma::load_matrix_sync(fbh[nf], bp, 40);
                            wmma::load_matrix_sync(fbl[nf], bp + 9 * 1280, 40);
                        }
                        #pragma unroll
                        for (int m = 0; m < 2; ++m)
                            #pragma unroll
                            for (int nf = 0; nf < 2; ++nf) {
                                wmma::mma_sync(acc[m][nf], ah[m], fbh[nf], acc[m][nf]);
                                wmma::mma_sync(acc[m][nf], al[m], fbh[nf], acc[m][nf]);
                                wmma::mma_sync(acc[m][nf], ah[m], fbl[nf], acc[m][nf]);
                            }
                    }
                }
            }

            // direct gmem store: col_major, i=px (stride 1), j=oc (stride 65536)
            int y = y0 + t;
            #pragma unroll
            for (int m = 0; m < 2; ++m)
                #pragma unroll
                for (int nf = 0; nf < 2; ++nf) {
                    float* op = out + (size_t)n * 2097152u
                              + (size_t)(nf * 16) * 65536u
                              + (size_t)y * 256u + (x0 + px0 + m * 16);
                    wmma::store_matrix_sync(op, acc[m][nf], 65536,
                                            wmma::mem_col_major);
                }
        } else if (t <= 30) {
            int r = t + 2;            // strip r -> slot (r+1)&3
            stage_strip(sA + ((r + 1) & 3) * SLOT_ELEMS, y0 + r, x0, xn,
                        tid - 128, 128);
        }
        __syncthreads();
    }
}

// ---------------------------------------------------------------------------
// Launch
// ---------------------------------------------------------------------------
extern "C" void kernel_launch(void* const* d_in, const int* in_sizes, int n_in,
                              void* d_out, int out_size) {
    const float* x    = nullptr;
    const float* wbar = nullptr;
    const float* bias = nullptr;
    for (int i = 0; i < n_in; ++i) {
        if (in_sizes[i] == 9216)      wbar = (const float*)d_in[i];
        else if (in_sizes[i] == 32)   bias = (const float*)d_in[i];
        else                          x    = (const float*)d_in[i];
    }

    sigma_kernel<<<1, 256>>>(wbar);

    cudaFuncSetAttribute(conv_wmma,
                         cudaFuncAttributeMaxDynamicSharedMemorySize,
                         SMEM_DYN);
    conv_wmma<<<512, 256, SMEM_DYN>>>(x, bias, (float*)d_out);
}

// round 16
// speedup vs baseline: 1.3615x; 1.3615x over previous
#include <cuda_runtime.h>
#include <cuda_bf16.h>
#include <mma.h>
#include <cstdint>

using namespace nvcuda;

typedef unsigned long long ULL;

// bf16 hi/lo split weights: [variant(0=hi,1=lo)][tap(9)][c(32)][oc(32)]
__device__ unsigned short g_bw[18432];

// ---------------------------------------------------------------------------
// Kernel 1: sigma = max(1, s1/2) via repeated squaring + Rayleigh quotient,
// then emit bf16 hi/lo split weights into g_bw (layout [v][tap][c][oc]).
// ---------------------------------------------------------------------------
#define WT_STRIDE 33

__global__ void sigma_kernel(const float* __restrict__ w_bar) {
    __shared__ float Wt[288 * WT_STRIDE];
    __shared__ float G0[1024];
    __shared__ float s_inv;

    int tid = threadIdx.x;

    for (int m = tid; m < 9216; m += 256) {
        int i = m / 288;
        int k = m - i * 288;
        Wt[k * WT_STRIDE + i] = w_bar[m];
    }
    __syncthreads();

    for (int e = tid; e < 1024; e += 256) {
        int i = e >> 5, j = e & 31;
        float s = 0.f;
        #pragma unroll 4
        for (int k = 0; k < 288; ++k)
            s += Wt[k * WT_STRIDE + i] * Wt[k * WT_STRIDE + j];
        G0[e] = s;
    }
    __syncthreads();

    float* bufA = Wt;
    float* bufB = Wt + 1024;

    const float* cur = G0;
    float* nxt = bufA;
    for (int it = 0; it < 14; ++it) {
        float tr = 0.f;
        #pragma unroll
        for (int d = 0; d < 32; ++d) tr += cur[d * 33];
        float inv = 1.0f / fmaxf(tr, 1e-30f);
        float inv2 = inv * inv;

        for (int e = tid; e < 1024; e += 256) {
            int i = e >> 5, j = e & 31;
            const float* ri = cur + i * 32;
            float s = 0.f;
            #pragma unroll
            for (int k = 0; k < 32; ++k) s += ri[k] * cur[k * 32 + j];
            nxt[e] = s * inv2;
        }
        __syncthreads();
        cur = nxt;
        nxt = (nxt == bufA) ? bufB : bufA;
    }

    if (tid < 32) {
        float d = cur[tid * 33];
        int jbest = tid;
        #pragma unroll
        for (int off = 16; off > 0; off >>= 1) {
            float od = __shfl_xor_sync(0xffffffffu, d, off);
            int   oj = __shfl_xor_sync(0xffffffffu, jbest, off);
            if (od > d) { d = od; jbest = oj; }
        }
        jbest = __shfl_sync(0xffffffffu, jbest, 0);

        float v = cur[tid * 32 + jbest];
        float gv = 0.f;
        const float* gi = G0 + tid * 32;
        #pragma unroll
        for (int j = 0; j < 32; ++j)
            gv += gi[j] * __shfl_sync(0xffffffffu, v, j);

        float num = v * gv, den = v * v;
        #pragma unroll
        for (int off = 16; off > 0; off >>= 1) {
            num += __shfl_xor_sync(0xffffffffu, num, off);
            den += __shfl_xor_sync(0xffffffffu, den, off);
        }
        if (tid == 0) {
            float lambda1 = num / fmaxf(den, 1e-30f);  // = s1^2
            float s1 = sqrtf(fmaxf(lambda1, 0.f));
            float sigma = fmaxf(1.0f, 0.5f * s1);
            s_inv = 1.0f / sigma;
        }
    }
    __syncthreads();

    float invs = s_inv;
    for (int i = tid; i < 9216; i += 256) {
        int oc  = i / 288;
        int rem = i - oc * 288;      // c*9 + ky*3 + kx
        int c   = rem / 9;
        int k9  = rem - c * 9;
        float w = w_bar[i] * invs;
        __nv_bfloat16 h = __float2bfloat16(w);
        float hv = __bfloat162float(h);
        __nv_bfloat16 l = __float2bfloat16(w - hv);
        int idx = (k9 * 32 + c) * 32 + oc;   // [tap][c][oc]
        g_bw[idx]        = __bfloat16_as_ushort(h);
        g_bw[idx + 9216] = __bfloat16_as_ushort(l);
    }
}

// ---------------------------------------------------------------------------
// Kernel 2: WMMA bf16 conv (3-term hi/lo split: xh*wh + xl*wh + xh*wl).
//
// Tile = TWO output rows per iteration; all 8 warps compute:
//   warp -> (row_sel = wid>>2, px quarter = wid&3), 32px x 32oc each.
// A ring: 6 slots, slot l%6 holds input row (y0-1+l) as hi/lo bf16 planes
// [130 px][40 c] (80B rows, conflict-free LDSM). Staging of the next two
// rows happens after compute in the same iteration (disjoint slots mod 6
// => single __syncthreads per iteration).
// B: 18 mats [c=32][oc, ldm 40] (hi taps 0..8, lo taps 9..17).
// mma order term->kt->m->nf: each acc revisited after 7 independent mmas.
// ---------------------------------------------------------------------------
#define SLOT_ELEMS 10400          // 2 planes x 130 x 40 bf16
#define PLANE      5200
#define NSLOT      6
#define B_ELEMS    23040          // 18 x 32 x 40
#define BIAS_F     640            // 2 tiles x 16 x 20 f32
#define SMEM_DYN   ((NSLOT * SLOT_ELEMS + B_ELEMS) * 2 + BIAS_F * 4)  // 173440

typedef wmma::fragment<wmma::matrix_a, 16, 16, 16, __nv_bfloat16, wmma::row_major> FragA;
typedef wmma::fragment<wmma::matrix_b, 16, 16, 16, __nv_bfloat16, wmma::row_major> FragB;
typedef wmma::fragment<wmma::accumulator, 16, 16, 16, float> FragC;

extern __shared__ __nv_bfloat16 s_bf[];

// stage input row `row` (global y) into ring slot `sl` as hi/lo bf16 planes
__device__ __forceinline__ void stage_strip(__nv_bfloat16* sl, int row, int x0,
                                            const float* xn, int lt, int nthr) {
    __nv_bfloat16* hi = sl;
    __nv_bfloat16* lo = sl + PLANE;
    bool rv = ((unsigned)row < 256u);
    const float* rp = xn + (rv ? row : 0) * 256;
    #pragma unroll 1
    for (int e = lt; e < 4160; e += nthr) {
        int c  = e / 130;
        int px = e - c * 130;
        int gx = x0 - 1 + px;
        float v = (rv && (unsigned)gx < 256u) ? __ldg(rp + c * 65536 + gx) : 0.f;
        __nv_bfloat16 h = __float2bfloat16(v);
        float hf = __bfloat162float(h);
        __nv_bfloat16 l = __float2bfloat16(v - hf);
        hi[px * 40 + c] = h;
        lo[px * 40 + c] = l;
    }
}

__global__ __launch_bounds__(256, 1)
void conv_wmma(const float* __restrict__ x,
               const float* __restrict__ bias,
               float* __restrict__ out) {
    __nv_bfloat16* sA = s_bf;                          // 6 slots
    __nv_bfloat16* sB = s_bf + NSLOT * SLOT_ELEMS;     // 18 mats
    float* sbias = (float*)(s_bf + NSLOT * SLOT_ELEMS + B_ELEMS);

    int tid = threadIdx.x, wid = tid >> 5;

    int bx = blockIdx.x;              // 512 CTAs
    int n  = bx >> 4;
    int xt = (bx >> 3) & 1;
    int yq = bx & 7;
    int x0 = xt * 128;
    int y0 = yq * 32;
    const float* xn = x + (size_t)n * 2097152u;

    // stage B (18 mats), bias tiles, and prologue strips l=0..3 (rows y0-1..y0+2)
    for (int e = tid; e < 18432; e += 256) {
        int mat = e >> 10;
        int c   = (e >> 5) & 31;
        int oc  = e & 31;
        sB[mat * 1280 + c * 40 + oc] = __ushort_as_bfloat16(g_bw[e]);
    }
    for (int e = tid; e < BIAS_F; e += 256) {
        int nf = e / 320;
        int j  = e % 20;
        sbias[e] = (j < 16) ? bias[nf * 16 + j] : 0.f;
    }
    #pragma unroll
    for (int l = 0; l < 4; ++l)
        stage_strip(sA + l * SLOT_ELEMS, y0 - 1 + l, x0, xn, tid, 256);
    __syncthreads();

    int rs  = wid >> 2;               // row select within the pair
    int px0 = (wid & 3) * 32;         // pixel quarter

    #pragma unroll 1
    for (int t = 0; t < 16; ++t) {
        FragC acc[2][2];
        #pragma unroll
        for (int m = 0; m < 2; ++m)
            #pragma unroll
            for (int nf = 0; nf < 2; ++nf)
                wmma::load_matrix_sync(acc[m][nf], sbias + nf * 320, 20,
                                       wmma::mem_row_major);

        #pragma unroll 1
        for (int ky = 0; ky < 3; ++ky) {
            int l = 2 * t + rs + ky;                    // local input row
            const __nv_bfloat16* slot = sA + (l % NSLOT) * SLOT_ELEMS;
            #pragma unroll 1
            for (int kx = 0; kx < 3; ++kx) {
                const __nv_bfloat16* bh = sB + (ky * 3 + kx) * 1280;

                // load all fragments for both kt halves up front
                FragA ah[2][2], al[2][2];               // [m][kt]
                #pragma unroll
                for (int m = 0; m < 2; ++m)
                    #pragma unroll
                    for (int kt = 0; kt < 2; ++kt) {
                        const __nv_bfloat16* ap =
                            slot + (px0 + m * 16 + kx) * 40 + kt * 16;
                        wmma::load_matrix_sync(ah[m][kt], ap, 40);
                        wmma::load_matrix_sync(al[m][kt], ap + PLANE, 40);
                    }
                FragB fbh[2][2], fbl[2][2];             // [kt][nf]
                #pragma unroll
                for (int kt = 0; kt < 2; ++kt)
                    #pragma unroll
                    for (int nf = 0; nf < 2; ++nf) {
                        const __nv_bfloat16* bp = bh + kt * 16 * 40 + nf * 16;
                        wmma::load_matrix_sync(fbh[kt][nf], bp, 40);
                        wmma::load_matrix_sync(fbl[kt][nf], bp + 9 * 1280, 40);
                    }

                // term 1: xh * wh   (acc revisit distance = 8 mmas)
                #pragma unroll
                for (int kt = 0; kt < 2; ++kt)
                    #pragma unroll
                    for (int m = 0; m < 2; ++m)
                        #pragma unroll
                        for (int nf = 0; nf < 2; ++nf)
                            wmma::mma_sync(acc[m][nf], ah[m][kt], fbh[kt][nf], acc[m][nf]);
                // term 2: xl * wh
                #pragma unroll
                for (int kt = 0; kt < 2; ++kt)
                    #pragma unroll
                    for (int m = 0; m < 2; ++m)
                        #pragma unroll
                        for (int nf = 0; nf < 2; ++nf)
                            wmma::mma_sync(acc[m][nf], al[m][kt], fbh[kt][nf], acc[m][nf]);
                // term 3: xh * wl
                #pragma unroll
                for (int kt = 0; kt < 2; ++kt)
                    #pragma unroll
                    for (int m = 0; m < 2; ++m)
                        #pragma unroll
                        for (int nf = 0; nf < 2; ++nf)
                            wmma::mma_sync(acc[m][nf], ah[m][kt], fbl[kt][nf], acc[m][nf]);
            }
        }

        // direct gmem store: col_major, i=px (stride 1), j=oc (stride 65536)
        int y = y0 + 2 * t + rs;
        #pragma unroll
        for (int m = 0; m < 2; ++m)
            #pragma unroll
            for (int nf = 0; nf < 2; ++nf) {
                float* op = out + (size_t)n * 2097152u
                          + (size_t)(nf * 16) * 65536u
                          + (size_t)y * 256u + (x0 + px0 + m * 16);
                wmma::store_matrix_sync(op, acc[m][nf], 65536,
                                        wmma::mem_col_major);
            }

        // stage rows for next iteration: l = 2t+4, 2t+5. These map to slots
        // (2t+4)%6, (2t+5)%6 which no warp reads during THIS iteration
        // (reads are l=2t..2t+3, all distinct mod 6), so one sync suffices.
        if (t < 15) {
            stage_strip(sA + ((2 * t + 4) % NSLOT) * SLOT_ELEMS,
                        y0 + 2 * t + 3, x0, xn, tid, 256);
            stage_strip(sA + ((2 * t + 5) % NSLOT) * SLOT_ELEMS,
                        y0 + 2 * t + 4, x0, xn, tid, 256);
        }
        __syncthreads();
    }
}

// ---------------------------------------------------------------------------
// Launch
// ---------------------------------------------------------------------------
extern "C" void kernel_launch(void* const* d_in, const int* in_sizes, int n_in,
                              void* d_out, int out_size) {
    const float* x    = nullptr;
    const float* wbar = nullptr;
    const float* bias = nullptr;
    for (int i = 0; i < n_in; ++i) {
        if (in_sizes[i] == 9216)      wbar = (const float*)d_in[i];
        else if (in_sizes[i] == 32)   bias = (const float*)d_in[i];
        else                          x    = (const float*)d_in[i];
    }

    sigma_kernel<<<1, 256>>>(wbar);

    cudaFuncSetAttribute(conv_wmma,
                         cudaFuncAttributeMaxDynamicSharedMemorySize,
                         SMEM_DYN);
    conv_wmma<<<512, 256, SMEM_DYN>>>(x, bias, (float*)d_out);
}